// round 15
// baseline (speedup 1.0000x reference)
#include <cuda_runtime.h>
#include <cuda_bf16.h>
#include <math_constants.h>

#define NV 8192
#define NF 16384
#define NP 16384
#define TPB 128
#define WPB (TPB / 32)
#define QCAP 256
#define NBLK 1184   // 8 blocks per SM on 148-SM B200 (64 regs * 128 thr = 8K regs)

// Packed per-triangle data: ax,ay,az, bx,by,bz, cx,cy,cz, nx,ny,nz
__device__ __align__(16) float g_tri[NF * 12];
// Plane cull data: unit normal xyz, w = -dot(a, n_hat). Zero if degenerate.
__device__ float4 g_plane[NF];
// Dynamic work counter (reset each launch in precompute_tris)
__device__ int g_ctr;

// ---------- strict IEEE helpers (bit-stable vs reference) ----------
__device__ __forceinline__ float dot3(float x0, float x1, float x2,
                                      float y0, float y1, float y2) {
    return __fadd_rn(__fadd_rn(__fmul_rn(x0, y0), __fmul_rn(x1, y1)),
                     __fmul_rn(x2, y2));
}
__device__ __forceinline__ float sdiv(float x, float y) {
    return __fdiv_rn(x, (y == 0.0f) ? 1.0f : y);
}

// ---------- kernel 1: triangle precompute (+ work counter reset) ----------
__global__ void precompute_tris(const float* __restrict__ vertices,
                                const int* __restrict__ faces) {
    int f = blockIdx.x * blockDim.x + threadIdx.x;
    if (f == 0) g_ctr = 0;
    if (f >= NF) return;
    int i0 = faces[f * 3 + 0];
    int i1 = faces[f * 3 + 1];
    int i2 = faces[f * 3 + 2];
    float ax = vertices[i0 * 3 + 0], ay = vertices[i0 * 3 + 1], az = vertices[i0 * 3 + 2];
    float bx = vertices[i1 * 3 + 0], by = vertices[i1 * 3 + 1], bz = vertices[i1 * 3 + 2];
    float cx = vertices[i2 * 3 + 0], cy = vertices[i2 * 3 + 1], cz = vertices[i2 * 3 + 2];
    float abx = __fsub_rn(bx, ax), aby = __fsub_rn(by, ay), abz = __fsub_rn(bz, az);
    float acx = __fsub_rn(cx, ax), acy = __fsub_rn(cy, ay), acz = __fsub_rn(cz, az);
    float nx = __fsub_rn(__fmul_rn(aby, acz), __fmul_rn(abz, acy));
    float ny = __fsub_rn(__fmul_rn(abz, acx), __fmul_rn(abx, acz));
    float nz = __fsub_rn(__fmul_rn(abx, acy), __fmul_rn(aby, acx));
    float* t = &g_tri[f * 12];
    t[0] = ax; t[1] = ay; t[2] = az;
    t[3] = bx; t[4] = by; t[5] = bz;
    t[6] = cx; t[7] = cy; t[8] = cz;
    t[9] = nx; t[10] = ny; t[11] = nz;

    float len2 = nx * nx + ny * ny + nz * nz;
    if (len2 > 0.0f) {
        float inv = rsqrtf(len2);
        float ux = nx * inv, uy = ny * inv, uz = nz * inv;
        float d = ax * ux + ay * uy + az * uz;
        g_plane[f] = make_float4(ux, uy, uz, -d);
    } else {
        g_plane[f] = make_float4(0.0f, 0.0f, 0.0f, 0.0f);  // never culled
    }
}

// Evaluate one triangle exactly (bit-identical to reference); update lane best.
__device__ __forceinline__ bool eval_tri(
    int fe, float px, float py, float pz,
    unsigned long long& best_key, float& best_sd)
{
    const float4* tq = reinterpret_cast<const float4*>(&g_tri[fe * 12]);
    float4 q0 = __ldg(&tq[0]);
    float4 q1 = __ldg(&tq[1]);
    float4 q2 = __ldg(&tq[2]);
    float ax = q0.x, ay = q0.y, az = q0.z;
    float bx = q0.w, by = q1.x, bz = q1.y;
    float cx = q1.z, cy = q1.w, cz = q2.x;
    float nx = q2.y, ny = q2.z, nz = q2.w;

    float abx = __fsub_rn(bx, ax), aby = __fsub_rn(by, ay), abz = __fsub_rn(bz, az);
    float acx = __fsub_rn(cx, ax), acy = __fsub_rn(cy, ay), acz = __fsub_rn(cz, az);
    float apx = __fsub_rn(px, ax), apy = __fsub_rn(py, ay), apz = __fsub_rn(pz, az);
    float bpx = __fsub_rn(px, bx), bpy = __fsub_rn(py, by), bpz = __fsub_rn(pz, bz);
    float cpx = __fsub_rn(px, cx), cpy = __fsub_rn(py, cy), cpz = __fsub_rn(pz, cz);

    float d1 = dot3(abx, aby, abz, apx, apy, apz);
    float d2 = dot3(acx, acy, acz, apx, apy, apz);
    float d3 = dot3(abx, aby, abz, bpx, bpy, bpz);
    float d4 = dot3(acx, acy, acz, bpx, bpy, bpz);
    float d5 = dot3(abx, aby, abz, cpx, cpy, cpz);
    float d6 = dot3(acx, acy, acz, cpx, cpy, cpz);

    float va = __fsub_rn(__fmul_rn(d3, d6), __fmul_rn(d5, d4));
    float vb = __fsub_rn(__fmul_rn(d5, d2), __fmul_rn(d1, d6));
    float vc = __fsub_rn(__fmul_rn(d1, d4), __fmul_rn(d3, d2));
    float denom = __fadd_rn(__fadd_rn(va, vb), vc);
    float v = sdiv(vb, denom);
    float w = sdiv(vc, denom);

    float e43 = __fsub_rn(d4, d3);
    float e56 = __fsub_rn(d5, d6);
    float t_bc = sdiv(e43, __fadd_rn(e43, e56));
    if (va <= 0.0f && e43 >= 0.0f && e56 >= 0.0f) {
        v = __fsub_rn(1.0f, t_bc); w = t_bc;
    }
    float t_ac = sdiv(d2, __fsub_rn(d2, d6));
    if (vb <= 0.0f && d2 >= 0.0f && d6 <= 0.0f) { v = 0.0f; w = t_ac; }
    float t_ab = sdiv(d1, __fsub_rn(d1, d3));
    if (vc <= 0.0f && d1 >= 0.0f && d3 <= 0.0f) { v = t_ab; w = 0.0f; }
    if (d6 >= 0.0f && d5 <= d6) { v = 0.0f; w = 1.0f; }
    if (d3 >= 0.0f && d4 <= d3) { v = 1.0f; w = 0.0f; }
    if (d1 <= 0.0f && d2 <= 0.0f) { v = 0.0f; w = 0.0f; }

    float clx = __fadd_rn(__fadd_rn(ax, __fmul_rn(v, abx)), __fmul_rn(w, acx));
    float cly = __fadd_rn(__fadd_rn(ay, __fmul_rn(v, aby)), __fmul_rn(w, acy));
    float clz = __fadd_rn(__fadd_rn(az, __fmul_rn(v, abz)), __fmul_rn(w, acz));
    float dx = __fsub_rn(px, clx);
    float dy = __fsub_rn(py, cly);
    float dz = __fsub_rn(pz, clz);
    float dist2 = dot3(dx, dy, dz, dx, dy, dz);

    unsigned long long key =
        ((unsigned long long)__float_as_uint(dist2) << 32) | (unsigned)fe;
    if (key < best_key) {
        best_key = key;
        best_sd = dot3(dx, dy, dz, nx, ny, nz);
        return true;
    }
    return false;
}

// ---------- kernel 2: persistent warps, min-tree fast path, 4-wide cull ------
__global__ void __launch_bounds__(TPB) sdf_main(const float* __restrict__ points,
                                                float* __restrict__ out) {
    __shared__ int queue[WPB][QCAP];

    int warp_in_blk = threadIdx.x / 32;
    int lane = threadIdx.x % 32;
    unsigned lanemask = (1u << lane) - 1u;

    for (;;) {
        int pid;
        if (lane == 0) pid = atomicAdd(&g_ctr, 1);
        pid = __shfl_sync(0xFFFFFFFFu, pid, 0);
        if (pid >= NP) break;

        float px = points[pid * 3 + 0];
        float py = points[pid * 3 + 1];
        float pz = points[pid * 3 + 2];

        // Seed: per-lane argmin over 16 strided vertex-a samples, then ONE
        // exact eval batch of the 32 argmin faces (collapses sq to near-true).
        float ub2 = CUDART_INF_F;
        int af = lane;
        #pragma unroll 4
        for (int i = 0; i < 16; i++) {
            int f = i * 1024 + lane * 32;   // spread over whole face range
            const float4* tq = reinterpret_cast<const float4*>(&g_tri[f * 12]);
            float4 q0 = __ldg(&tq[0]);
            float dx = px - q0.x, dy = py - q0.y, dz = pz - q0.z;
            float d2 = fmaf(dx, dx, fmaf(dy, dy, dz * dz));
            if (d2 < ub2) { ub2 = d2; af = f; }
        }
        unsigned long long best_key = 0xFFFFFFFFFFFFFFFFull;
        float best_sd = 0.0f;
        eval_tri(af, px, py, pz, best_key, best_sd);
        float bd2 = __uint_as_float((unsigned)(best_key >> 32));
        #pragma unroll
        for (int o = 16; o > 0; o >>= 1)
            bd2 = fminf(bd2, __shfl_xor_sync(0xFFFFFFFFu, bd2, o));
        float sq = fmaf(sqrtf(bd2), 1.001f, 1e-6f);

        int qn = 0, qhead = 0;

        // Prime the prefetch pipeline
        float4 pl0 = __ldg(&g_plane[lane]);
        float4 pl1 = __ldg(&g_plane[lane + 32]);
        float4 pl2 = __ldg(&g_plane[lane + 64]);
        float4 pl3 = __ldg(&g_plane[lane + 96]);

        for (int chunk = 0; chunk < NF; chunk += 128) {
            float pd0 = fmaf(px, pl0.x, fmaf(py, pl0.y, fmaf(pz, pl0.z, pl0.w)));
            float pd1 = fmaf(px, pl1.x, fmaf(py, pl1.y, fmaf(pz, pl1.z, pl1.w)));
            float pd2 = fmaf(px, pl2.x, fmaf(py, pl2.y, fmaf(pz, pl2.z, pl2.w)));
            float pd3 = fmaf(px, pl3.x, fmaf(py, pl3.y, fmaf(pz, pl3.z, pl3.w)));
            // min-tree any-test: |·| folds into FMNMX operand modifiers
            float mn = fminf(fminf(fabsf(pd0), fabsf(pd1)),
                             fminf(fabsf(pd2), fabsf(pd3)));

            // Save current planes for slow path before overwriting via prefetch
            float a0 = fabsf(pd0), a1 = fabsf(pd1), a2 = fabsf(pd2), a3 = fabsf(pd3);

            // Prefetch next chunk's planes
            int nxt = chunk + 128;
            if (nxt < NF) {
                pl0 = __ldg(&g_plane[nxt + lane]);
                pl1 = __ldg(&g_plane[nxt + lane + 32]);
                pl2 = __ldg(&g_plane[nxt + lane + 64]);
                pl3 = __ldg(&g_plane[nxt + lane + 96]);
            }

            // Fast path: most chunks have zero survivors warp-wide
            if (!__ballot_sync(0xFFFFFFFFu, mn <= sq)) continue;

            bool k0 = (a0 <= sq);
            bool k1 = (a1 <= sq);
            bool k2 = (a2 <= sq);
            bool k3 = (a3 <= sq);
            unsigned m0 = __ballot_sync(0xFFFFFFFFu, k0);
            unsigned m1 = __ballot_sync(0xFFFFFFFFu, k1);
            unsigned m2 = __ballot_sync(0xFFFFFFFFu, k2);
            unsigned m3 = __ballot_sync(0xFFFFFFFFu, k3);
            int n0 = __popc(m0);
            int n1 = __popc(m1);
            int n2 = __popc(m2);
            if (k0) queue[warp_in_blk][(qhead + qn + __popc(m0 & lanemask)) & (QCAP - 1)] = chunk + lane;
            if (k1) queue[warp_in_blk][(qhead + qn + n0 + __popc(m1 & lanemask)) & (QCAP - 1)] = chunk + lane + 32;
            if (k2) queue[warp_in_blk][(qhead + qn + n0 + n1 + __popc(m2 & lanemask)) & (QCAP - 1)] = chunk + lane + 64;
            if (k3) queue[warp_in_blk][(qhead + qn + n0 + n1 + n2 + __popc(m3 & lanemask)) & (QCAP - 1)] = chunk + lane + 96;
            qn += n0 + n1 + n2 + __popc(m3);
            __syncwarp();

            while (qn >= 32) {
                int fe = queue[warp_in_blk][(qhead + lane) & (QCAP - 1)];
                qhead += 32;
                qn -= 32;
                bool improved = eval_tri(fe, px, py, pz, best_key, best_sd);
                if (__ballot_sync(0xFFFFFFFFu, improved)) {
                    float b2 = __uint_as_float((unsigned)(best_key >> 32));
                    #pragma unroll
                    for (int o = 16; o > 0; o >>= 1)
                        b2 = fminf(b2, __shfl_xor_sync(0xFFFFFFFFu, b2, o));
                    sq = fminf(sq, fmaf(sqrtf(b2), 1.001f, 1e-6f));
                }
            }
            __syncwarp();
        }

        // Drain remaining queued survivors
        if (lane < qn) {
            int fe = queue[warp_in_blk][(qhead + lane) & (QCAP - 1)];
            eval_tri(fe, px, py, pz, best_key, best_sd);
        }
        __syncwarp();

        // Warp-reduce (key, sd) lexicographic min — argmin first-index tie-break
        #pragma unroll
        for (int o = 16; o > 0; o >>= 1) {
            unsigned long long ok = __shfl_xor_sync(0xFFFFFFFFu, best_key, o);
            float osd = __shfl_xor_sync(0xFFFFFFFFu, best_sd, o);
            if (ok < best_key) { best_key = ok; best_sd = osd; }
        }

        if (lane == 0) {
            float dist2 = __uint_as_float((unsigned)(best_key >> 32));
            float dist = sqrtf(fmaxf(dist2, 1e-12f));
            out[pid] = (best_sd > 0.0f) ? -dist : dist;
        }
    }
}

extern "C" void kernel_launch(void* const* d_in, const int* in_sizes, int n_in,
                              void* d_out, int out_size) {
    const float* points   = (const float*)d_in[0];
    const float* vertices = (const float*)d_in[1];
    const int*   faces    = (const int*)d_in[2];
    float* out = (float*)d_out;

    precompute_tris<<<(NF + 255) / 256, 256>>>(vertices, faces);
    sdf_main<<<NBLK, TPB>>>(points, out);
}

// round 16
// speedup vs baseline: 1.1231x; 1.1231x over previous
#include <cuda_runtime.h>
#include <cuda_bf16.h>
#include <math_constants.h>

#define NV 8192
#define NF 16384
#define NP 16384
#define TPB 128
#define WPB (TPB / 32)
#define QCAP 256
#define NBLK 888   // 6 blocks/SM at ~80 regs, persistent

// Packed per-triangle data: ax,ay,az, bx,by,bz, cx,cy,cz, nx,ny,nz
__device__ __align__(16) float g_tri[NF * 12];
// Plane cull data: unit normal xyz, w = -dot(a, n_hat). Zero if degenerate.
__device__ float4 g_plane[NF];
// Dynamic work counter (pairs), reset each launch in precompute_tris
__device__ int g_ctr;

// ---------- strict IEEE helpers (bit-stable vs reference) ----------
__device__ __forceinline__ float dot3(float x0, float x1, float x2,
                                      float y0, float y1, float y2) {
    return __fadd_rn(__fadd_rn(__fmul_rn(x0, y0), __fmul_rn(x1, y1)),
                     __fmul_rn(x2, y2));
}
__device__ __forceinline__ float sdiv(float x, float y) {
    return __fdiv_rn(x, (y == 0.0f) ? 1.0f : y);
}

// ---------- kernel 1: triangle precompute (+ work counter reset) ----------
__global__ void precompute_tris(const float* __restrict__ vertices,
                                const int* __restrict__ faces) {
    int f = blockIdx.x * blockDim.x + threadIdx.x;
    if (f == 0) g_ctr = 0;
    if (f >= NF) return;
    int i0 = faces[f * 3 + 0];
    int i1 = faces[f * 3 + 1];
    int i2 = faces[f * 3 + 2];
    float ax = vertices[i0 * 3 + 0], ay = vertices[i0 * 3 + 1], az = vertices[i0 * 3 + 2];
    float bx = vertices[i1 * 3 + 0], by = vertices[i1 * 3 + 1], bz = vertices[i1 * 3 + 2];
    float cx = vertices[i2 * 3 + 0], cy = vertices[i2 * 3 + 1], cz = vertices[i2 * 3 + 2];
    float abx = __fsub_rn(bx, ax), aby = __fsub_rn(by, ay), abz = __fsub_rn(bz, az);
    float acx = __fsub_rn(cx, ax), acy = __fsub_rn(cy, ay), acz = __fsub_rn(cz, az);
    float nx = __fsub_rn(__fmul_rn(aby, acz), __fmul_rn(abz, acy));
    float ny = __fsub_rn(__fmul_rn(abz, acx), __fmul_rn(abx, acz));
    float nz = __fsub_rn(__fmul_rn(abx, acy), __fmul_rn(aby, acx));
    float* t = &g_tri[f * 12];
    t[0] = ax; t[1] = ay; t[2] = az;
    t[3] = bx; t[4] = by; t[5] = bz;
    t[6] = cx; t[7] = cy; t[8] = cz;
    t[9] = nx; t[10] = ny; t[11] = nz;

    float len2 = nx * nx + ny * ny + nz * nz;
    if (len2 > 0.0f) {
        float inv = rsqrtf(len2);
        float ux = nx * inv, uy = ny * inv, uz = nz * inv;
        float d = ax * ux + ay * uy + az * uz;
        g_plane[f] = make_float4(ux, uy, uz, -d);
    } else {
        g_plane[f] = make_float4(0.0f, 0.0f, 0.0f, 0.0f);  // never culled
    }
}

// Evaluate one triangle exactly (bit-identical to reference); update lane best.
__device__ __forceinline__ bool eval_tri(
    int fe, float px, float py, float pz,
    unsigned long long& best_key, float& best_sd)
{
    const float4* tq = reinterpret_cast<const float4*>(&g_tri[fe * 12]);
    float4 q0 = __ldg(&tq[0]);
    float4 q1 = __ldg(&tq[1]);
    float4 q2 = __ldg(&tq[2]);
    float ax = q0.x, ay = q0.y, az = q0.z;
    float bx = q0.w, by = q1.x, bz = q1.y;
    float cx = q1.z, cy = q1.w, cz = q2.x;
    float nx = q2.y, ny = q2.z, nz = q2.w;

    float abx = __fsub_rn(bx, ax), aby = __fsub_rn(by, ay), abz = __fsub_rn(bz, az);
    float acx = __fsub_rn(cx, ax), acy = __fsub_rn(cy, ay), acz = __fsub_rn(cz, az);
    float apx = __fsub_rn(px, ax), apy = __fsub_rn(py, ay), apz = __fsub_rn(pz, az);
    float bpx = __fsub_rn(px, bx), bpy = __fsub_rn(py, by), bpz = __fsub_rn(pz, bz);
    float cpx = __fsub_rn(px, cx), cpy = __fsub_rn(py, cy), cpz = __fsub_rn(pz, cz);

    float d1 = dot3(abx, aby, abz, apx, apy, apz);
    float d2 = dot3(acx, acy, acz, apx, apy, apz);
    float d3 = dot3(abx, aby, abz, bpx, bpy, bpz);
    float d4 = dot3(acx, acy, acz, bpx, bpy, bpz);
    float d5 = dot3(abx, aby, abz, cpx, cpy, cpz);
    float d6 = dot3(acx, acy, acz, cpx, cpy, cpz);

    float va = __fsub_rn(__fmul_rn(d3, d6), __fmul_rn(d5, d4));
    float vb = __fsub_rn(__fmul_rn(d5, d2), __fmul_rn(d1, d6));
    float vc = __fsub_rn(__fmul_rn(d1, d4), __fmul_rn(d3, d2));
    float denom = __fadd_rn(__fadd_rn(va, vb), vc);
    float v = sdiv(vb, denom);
    float w = sdiv(vc, denom);

    float e43 = __fsub_rn(d4, d3);
    float e56 = __fsub_rn(d5, d6);
    float t_bc = sdiv(e43, __fadd_rn(e43, e56));
    if (va <= 0.0f && e43 >= 0.0f && e56 >= 0.0f) {
        v = __fsub_rn(1.0f, t_bc); w = t_bc;
    }
    float t_ac = sdiv(d2, __fsub_rn(d2, d6));
    if (vb <= 0.0f && d2 >= 0.0f && d6 <= 0.0f) { v = 0.0f; w = t_ac; }
    float t_ab = sdiv(d1, __fsub_rn(d1, d3));
    if (vc <= 0.0f && d1 >= 0.0f && d3 <= 0.0f) { v = t_ab; w = 0.0f; }
    if (d6 >= 0.0f && d5 <= d6) { v = 0.0f; w = 1.0f; }
    if (d3 >= 0.0f && d4 <= d3) { v = 1.0f; w = 0.0f; }
    if (d1 <= 0.0f && d2 <= 0.0f) { v = 0.0f; w = 0.0f; }

    float clx = __fadd_rn(__fadd_rn(ax, __fmul_rn(v, abx)), __fmul_rn(w, acx));
    float cly = __fadd_rn(__fadd_rn(ay, __fmul_rn(v, aby)), __fmul_rn(w, acy));
    float clz = __fadd_rn(__fadd_rn(az, __fmul_rn(v, abz)), __fmul_rn(w, acz));
    float dx = __fsub_rn(px, clx);
    float dy = __fsub_rn(py, cly);
    float dz = __fsub_rn(pz, clz);
    float dist2 = dot3(dx, dy, dz, dx, dy, dz);

    unsigned long long key =
        ((unsigned long long)__float_as_uint(dist2) << 32) | (unsigned)fe;
    if (key < best_key) {
        best_key = key;
        best_sd = dot3(dx, dy, dz, nx, ny, nz);
        return true;
    }
    return false;
}

__device__ __forceinline__ void tighten(unsigned long long best_key, float& sq) {
    float bd2 = __uint_as_float((unsigned)(best_key >> 32));
    #pragma unroll
    for (int o = 16; o > 0; o >>= 1)
        bd2 = fminf(bd2, __shfl_xor_sync(0xFFFFFFFFu, bd2, o));
    sq = fminf(sq, fmaf(sqrtf(bd2), 1.001f, 1e-6f));
}

// ---------- kernel 2: PERSISTENT warps, TWO points per grab, shared cull -----
__global__ void __launch_bounds__(TPB) sdf_main(const float* __restrict__ points,
                                                float* __restrict__ out) {
    __shared__ int queueA[WPB][QCAP];
    __shared__ int queueB[WPB][QCAP];

    int w = threadIdx.x / 32;
    int lane = threadIdx.x % 32;
    unsigned lanemask = (1u << lane) - 1u;

    for (;;) {
        int pairidx;
        if (lane == 0) pairidx = atomicAdd(&g_ctr, 1);
        pairidx = __shfl_sync(0xFFFFFFFFu, pairidx, 0);
        if (pairidx >= NP / 2) break;
        int pid0 = 2 * pairidx;
        int pid1 = 2 * pairidx + 1;

        float px0 = points[pid0 * 3 + 0], py0 = points[pid0 * 3 + 1], pz0 = points[pid0 * 3 + 2];
        float px1 = points[pid1 * 3 + 0], py1 = points[pid1 * 3 + 1], pz1 = points[pid1 * 3 + 2];

        // Seed upper bounds from 1024 vertex-a distances (shared, coalesced)
        float ubA = CUDART_INF_F, ubB = CUDART_INF_F;
        #pragma unroll 4
        for (int i = 0; i < 32; i++) {
            int f = i * 32 + lane;
            const float4* tq = reinterpret_cast<const float4*>(&g_tri[f * 12]);
            float4 q0 = __ldg(&tq[0]);
            float dxa = px0 - q0.x, dya = py0 - q0.y, dza = pz0 - q0.z;
            float dxb = px1 - q0.x, dyb = py1 - q0.y, dzb = pz1 - q0.z;
            ubA = fminf(ubA, fmaf(dxa, dxa, fmaf(dya, dya, dza * dza)));
            ubB = fminf(ubB, fmaf(dxb, dxb, fmaf(dyb, dyb, dzb * dzb)));
        }
        #pragma unroll
        for (int o = 16; o > 0; o >>= 1) {
            ubA = fminf(ubA, __shfl_xor_sync(0xFFFFFFFFu, ubA, o));
            ubB = fminf(ubB, __shfl_xor_sync(0xFFFFFFFFu, ubB, o));
        }
        float sq0 = fmaf(sqrtf(ubA), 1.001f, 1e-6f);
        float sq1 = fmaf(sqrtf(ubB), 1.001f, 1e-6f);

        unsigned long long bk0 = 0xFFFFFFFFFFFFFFFFull, bk1 = 0xFFFFFFFFFFFFFFFFull;
        float bs0 = 0.0f, bs1 = 0.0f;

        int qnA = 0, qhA = 0, qnB = 0, qhB = 0;

        // Prime the prefetch pipeline
        float4 pl0 = __ldg(&g_plane[lane]);
        float4 pl1 = __ldg(&g_plane[lane + 32]);
        float4 pl2 = __ldg(&g_plane[lane + 64]);
        float4 pl3 = __ldg(&g_plane[lane + 96]);

        for (int chunk = 0; chunk < NF; chunk += 128) {
            // 4 planes x 2 points = 8 independent FMA chains
            float s00 = fmaf(px0, pl0.x, fmaf(py0, pl0.y, fmaf(pz0, pl0.z, pl0.w)));
            float s01 = fmaf(px0, pl1.x, fmaf(py0, pl1.y, fmaf(pz0, pl1.z, pl1.w)));
            float s02 = fmaf(px0, pl2.x, fmaf(py0, pl2.y, fmaf(pz0, pl2.z, pl2.w)));
            float s03 = fmaf(px0, pl3.x, fmaf(py0, pl3.y, fmaf(pz0, pl3.z, pl3.w)));
            float s10 = fmaf(px1, pl0.x, fmaf(py1, pl0.y, fmaf(pz1, pl0.z, pl0.w)));
            float s11 = fmaf(px1, pl1.x, fmaf(py1, pl1.y, fmaf(pz1, pl1.z, pl1.w)));
            float s12 = fmaf(px1, pl2.x, fmaf(py1, pl2.y, fmaf(pz1, pl2.z, pl2.w)));
            float s13 = fmaf(px1, pl3.x, fmaf(py1, pl3.y, fmaf(pz1, pl3.z, pl3.w)));
            bool a0 = (fabsf(s00) <= sq0);
            bool a1 = (fabsf(s01) <= sq0);
            bool a2 = (fabsf(s02) <= sq0);
            bool a3 = (fabsf(s03) <= sq0);
            bool b0 = (fabsf(s10) <= sq1);
            bool b1 = (fabsf(s11) <= sq1);
            bool b2 = (fabsf(s12) <= sq1);
            bool b3 = (fabsf(s13) <= sq1);

            // Prefetch next chunk's planes
            int nxt = chunk + 128;
            if (nxt < NF) {
                pl0 = __ldg(&g_plane[nxt + lane]);
                pl1 = __ldg(&g_plane[nxt + lane + 32]);
                pl2 = __ldg(&g_plane[nxt + lane + 64]);
                pl3 = __ldg(&g_plane[nxt + lane + 96]);
            }

            // Fast path: zero survivors for both points warp-wide
            if (!__ballot_sync(0xFFFFFFFFu, a0 | a1 | a2 | a3 | b0 | b1 | b2 | b3))
                continue;

            // Point A compaction
            {
                unsigned m0 = __ballot_sync(0xFFFFFFFFu, a0);
                unsigned m1 = __ballot_sync(0xFFFFFFFFu, a1);
                unsigned m2 = __ballot_sync(0xFFFFFFFFu, a2);
                unsigned m3 = __ballot_sync(0xFFFFFFFFu, a3);
                int n0 = __popc(m0);
                int n1 = __popc(m1);
                int n2 = __popc(m2);
                if (a0) queueA[w][(qhA + qnA + __popc(m0 & lanemask)) & (QCAP - 1)] = chunk + lane;
                if (a1) queueA[w][(qhA + qnA + n0 + __popc(m1 & lanemask)) & (QCAP - 1)] = chunk + lane + 32;
                if (a2) queueA[w][(qhA + qnA + n0 + n1 + __popc(m2 & lanemask)) & (QCAP - 1)] = chunk + lane + 64;
                if (a3) queueA[w][(qhA + qnA + n0 + n1 + n2 + __popc(m3 & lanemask)) & (QCAP - 1)] = chunk + lane + 96;
                qnA += n0 + n1 + n2 + __popc(m3);
            }
            // Point B compaction
            {
                unsigned m0 = __ballot_sync(0xFFFFFFFFu, b0);
                unsigned m1 = __ballot_sync(0xFFFFFFFFu, b1);
                unsigned m2 = __ballot_sync(0xFFFFFFFFu, b2);
                unsigned m3 = __ballot_sync(0xFFFFFFFFu, b3);
                int n0 = __popc(m0);
                int n1 = __popc(m1);
                int n2 = __popc(m2);
                if (b0) queueB[w][(qhB + qnB + __popc(m0 & lanemask)) & (QCAP - 1)] = chunk + lane;
                if (b1) queueB[w][(qhB + qnB + n0 + __popc(m1 & lanemask)) & (QCAP - 1)] = chunk + lane + 32;
                if (b2) queueB[w][(qhB + qnB + n0 + n1 + __popc(m2 & lanemask)) & (QCAP - 1)] = chunk + lane + 64;
                if (b3) queueB[w][(qhB + qnB + n0 + n1 + n2 + __popc(m3 & lanemask)) & (QCAP - 1)] = chunk + lane + 96;
                qnB += n0 + n1 + n2 + __popc(m3);
            }
            __syncwarp();

            while (qnA >= 32) {
                int fe = queueA[w][(qhA + lane) & (QCAP - 1)];
                qhA += 32;
                qnA -= 32;
                bool imp = eval_tri(fe, px0, py0, pz0, bk0, bs0);
                if (__ballot_sync(0xFFFFFFFFu, imp)) tighten(bk0, sq0);
            }
            while (qnB >= 32) {
                int fe = queueB[w][(qhB + lane) & (QCAP - 1)];
                qhB += 32;
                qnB -= 32;
                bool imp = eval_tri(fe, px1, py1, pz1, bk1, bs1);
                if (__ballot_sync(0xFFFFFFFFu, imp)) tighten(bk1, sq1);
            }
            __syncwarp();
        }

        // Drain leftovers
        if (lane < qnA) {
            int fe = queueA[w][(qhA + lane) & (QCAP - 1)];
            eval_tri(fe, px0, py0, pz0, bk0, bs0);
        }
        if (lane < qnB) {
            int fe = queueB[w][(qhB + lane) & (QCAP - 1)];
            eval_tri(fe, px1, py1, pz1, bk1, bs1);
        }
        __syncwarp();

        // Warp-reduce both (key, sd) lexicographic mins — argmin tie-break
        #pragma unroll
        for (int o = 16; o > 0; o >>= 1) {
            unsigned long long ok = __shfl_xor_sync(0xFFFFFFFFu, bk0, o);
            float osd = __shfl_xor_sync(0xFFFFFFFFu, bs0, o);
            if (ok < bk0) { bk0 = ok; bs0 = osd; }
            unsigned long long ok1 = __shfl_xor_sync(0xFFFFFFFFu, bk1, o);
            float osd1 = __shfl_xor_sync(0xFFFFFFFFu, bs1, o);
            if (ok1 < bk1) { bk1 = ok1; bs1 = osd1; }
        }

        if (lane == 0) {
            float d20 = __uint_as_float((unsigned)(bk0 >> 32));
            float dist0 = sqrtf(fmaxf(d20, 1e-12f));
            out[pid0] = (bs0 > 0.0f) ? -dist0 : dist0;
            float d21 = __uint_as_float((unsigned)(bk1 >> 32));
            float dist1 = sqrtf(fmaxf(d21, 1e-12f));
            out[pid1] = (bs1 > 0.0f) ? -dist1 : dist1;
        }
    }
}

extern "C" void kernel_launch(void* const* d_in, const int* in_sizes, int n_in,
                              void* d_out, int out_size) {
    const float* points   = (const float*)d_in[0];
    const float* vertices = (const float*)d_in[1];
    const int*   faces    = (const int*)d_in[2];
    float* out = (float*)d_out;

    precompute_tris<<<(NF + 255) / 256, 256>>>(vertices, faces);
    sdf_main<<<NBLK, TPB>>>(points, out);
}

// round 17
// speedup vs baseline: 1.1600x; 1.0329x over previous
#include <cuda_runtime.h>
#include <cuda_bf16.h>
#include <math_constants.h>

#define NV 8192
#define NF 16384
#define NP 16384
#define TPB 128
#define WPB (TPB / 32)
#define QCAP 256
#define NBLK 1036   // 7 blocks/SM at 72 regs on 148-SM B200, persistent

// Packed per-triangle data: ax,ay,az, bx,by,bz, cx,cy,cz, nx,ny,nz
__device__ __align__(16) float g_tri[NF * 12];
// Plane cull data: unit normal xyz, w = -dot(a, n_hat). Zero if degenerate.
__device__ float4 g_plane[NF];
// Dynamic work counter (pairs), reset each launch in precompute_tris
__device__ int g_ctr;

// ---------- strict IEEE helpers (bit-stable vs reference) ----------
__device__ __forceinline__ float dot3(float x0, float x1, float x2,
                                      float y0, float y1, float y2) {
    return __fadd_rn(__fadd_rn(__fmul_rn(x0, y0), __fmul_rn(x1, y1)),
                     __fmul_rn(x2, y2));
}
__device__ __forceinline__ float sdiv(float x, float y) {
    return __fdiv_rn(x, (y == 0.0f) ? 1.0f : y);
}

// ---------- kernel 1: triangle precompute (+ work counter reset) ----------
__global__ void precompute_tris(const float* __restrict__ vertices,
                                const int* __restrict__ faces) {
    int f = blockIdx.x * blockDim.x + threadIdx.x;
    if (f == 0) g_ctr = 0;
    if (f >= NF) return;
    int i0 = faces[f * 3 + 0];
    int i1 = faces[f * 3 + 1];
    int i2 = faces[f * 3 + 2];
    float ax = vertices[i0 * 3 + 0], ay = vertices[i0 * 3 + 1], az = vertices[i0 * 3 + 2];
    float bx = vertices[i1 * 3 + 0], by = vertices[i1 * 3 + 1], bz = vertices[i1 * 3 + 2];
    float cx = vertices[i2 * 3 + 0], cy = vertices[i2 * 3 + 1], cz = vertices[i2 * 3 + 2];
    float abx = __fsub_rn(bx, ax), aby = __fsub_rn(by, ay), abz = __fsub_rn(bz, az);
    float acx = __fsub_rn(cx, ax), acy = __fsub_rn(cy, ay), acz = __fsub_rn(cz, az);
    float nx = __fsub_rn(__fmul_rn(aby, acz), __fmul_rn(abz, acy));
    float ny = __fsub_rn(__fmul_rn(abz, acx), __fmul_rn(abx, acz));
    float nz = __fsub_rn(__fmul_rn(abx, acy), __fmul_rn(aby, acx));
    float* t = &g_tri[f * 12];
    t[0] = ax; t[1] = ay; t[2] = az;
    t[3] = bx; t[4] = by; t[5] = bz;
    t[6] = cx; t[7] = cy; t[8] = cz;
    t[9] = nx; t[10] = ny; t[11] = nz;

    float len2 = nx * nx + ny * ny + nz * nz;
    if (len2 > 0.0f) {
        float inv = rsqrtf(len2);
        float ux = nx * inv, uy = ny * inv, uz = nz * inv;
        float d = ax * ux + ay * uy + az * uz;
        g_plane[f] = make_float4(ux, uy, uz, -d);
    } else {
        g_plane[f] = make_float4(0.0f, 0.0f, 0.0f, 0.0f);  // never culled
    }
}

// Evaluate one triangle exactly (bit-identical to reference); update lane best.
__device__ __forceinline__ bool eval_tri(
    int fe, float px, float py, float pz,
    unsigned long long& best_key, float& best_sd)
{
    const float4* tq = reinterpret_cast<const float4*>(&g_tri[fe * 12]);
    float4 q0 = __ldg(&tq[0]);
    float4 q1 = __ldg(&tq[1]);
    float4 q2 = __ldg(&tq[2]);
    float ax = q0.x, ay = q0.y, az = q0.z;
    float bx = q0.w, by = q1.x, bz = q1.y;
    float cx = q1.z, cy = q1.w, cz = q2.x;
    float nx = q2.y, ny = q2.z, nz = q2.w;

    float abx = __fsub_rn(bx, ax), aby = __fsub_rn(by, ay), abz = __fsub_rn(bz, az);
    float acx = __fsub_rn(cx, ax), acy = __fsub_rn(cy, ay), acz = __fsub_rn(cz, az);
    float apx = __fsub_rn(px, ax), apy = __fsub_rn(py, ay), apz = __fsub_rn(pz, az);
    float bpx = __fsub_rn(px, bx), bpy = __fsub_rn(py, by), bpz = __fsub_rn(pz, bz);
    float cpx = __fsub_rn(px, cx), cpy = __fsub_rn(py, cy), cpz = __fsub_rn(pz, cz);

    float d1 = dot3(abx, aby, abz, apx, apy, apz);
    float d2 = dot3(acx, acy, acz, apx, apy, apz);
    float d3 = dot3(abx, aby, abz, bpx, bpy, bpz);
    float d4 = dot3(acx, acy, acz, bpx, bpy, bpz);
    float d5 = dot3(abx, aby, abz, cpx, cpy, cpz);
    float d6 = dot3(acx, acy, acz, cpx, cpy, cpz);

    float va = __fsub_rn(__fmul_rn(d3, d6), __fmul_rn(d5, d4));
    float vb = __fsub_rn(__fmul_rn(d5, d2), __fmul_rn(d1, d6));
    float vc = __fsub_rn(__fmul_rn(d1, d4), __fmul_rn(d3, d2));
    float denom = __fadd_rn(__fadd_rn(va, vb), vc);
    float v = sdiv(vb, denom);
    float w = sdiv(vc, denom);

    float e43 = __fsub_rn(d4, d3);
    float e56 = __fsub_rn(d5, d6);
    float t_bc = sdiv(e43, __fadd_rn(e43, e56));
    if (va <= 0.0f && e43 >= 0.0f && e56 >= 0.0f) {
        v = __fsub_rn(1.0f, t_bc); w = t_bc;
    }
    float t_ac = sdiv(d2, __fsub_rn(d2, d6));
    if (vb <= 0.0f && d2 >= 0.0f && d6 <= 0.0f) { v = 0.0f; w = t_ac; }
    float t_ab = sdiv(d1, __fsub_rn(d1, d3));
    if (vc <= 0.0f && d1 >= 0.0f && d3 <= 0.0f) { v = t_ab; w = 0.0f; }
    if (d6 >= 0.0f && d5 <= d6) { v = 0.0f; w = 1.0f; }
    if (d3 >= 0.0f && d4 <= d3) { v = 1.0f; w = 0.0f; }
    if (d1 <= 0.0f && d2 <= 0.0f) { v = 0.0f; w = 0.0f; }

    float clx = __fadd_rn(__fadd_rn(ax, __fmul_rn(v, abx)), __fmul_rn(w, acx));
    float cly = __fadd_rn(__fadd_rn(ay, __fmul_rn(v, aby)), __fmul_rn(w, acy));
    float clz = __fadd_rn(__fadd_rn(az, __fmul_rn(v, abz)), __fmul_rn(w, acz));
    float dx = __fsub_rn(px, clx);
    float dy = __fsub_rn(py, cly);
    float dz = __fsub_rn(pz, clz);
    float dist2 = dot3(dx, dy, dz, dx, dy, dz);

    unsigned long long key =
        ((unsigned long long)__float_as_uint(dist2) << 32) | (unsigned)fe;
    if (key < best_key) {
        best_key = key;
        best_sd = dot3(dx, dy, dz, nx, ny, nz);
        return true;
    }
    return false;
}

__device__ __forceinline__ void tighten(unsigned long long best_key, float& sq) {
    float bd2 = __uint_as_float((unsigned)(best_key >> 32));
    #pragma unroll
    for (int o = 16; o > 0; o >>= 1)
        bd2 = fminf(bd2, __shfl_xor_sync(0xFFFFFFFFu, bd2, o));
    sq = fminf(sq, fmaf(sqrtf(bd2), 1.001f, 1e-6f));
}

// ---------- kernel 2: PERSISTENT warps, TWO points per grab, shared cull -----
__global__ void __launch_bounds__(TPB) sdf_main(const float* __restrict__ points,
                                                float* __restrict__ out) {
    __shared__ int queueA[WPB][QCAP];
    __shared__ int queueB[WPB][QCAP];

    int w = threadIdx.x / 32;
    int lane = threadIdx.x % 32;
    unsigned lanemask = (1u << lane) - 1u;

    for (;;) {
        int pairidx;
        if (lane == 0) pairidx = atomicAdd(&g_ctr, 1);
        pairidx = __shfl_sync(0xFFFFFFFFu, pairidx, 0);
        if (pairidx >= NP / 2) break;
        int pid0 = 2 * pairidx;
        int pid1 = 2 * pairidx + 1;

        float px0 = points[pid0 * 3 + 0], py0 = points[pid0 * 3 + 1], pz0 = points[pid0 * 3 + 2];
        float px1 = points[pid1 * 3 + 0], py1 = points[pid1 * 3 + 1], pz1 = points[pid1 * 3 + 2];

        // Seed upper bounds from 1024 vertex-a distances (shared, coalesced)
        float ubA = CUDART_INF_F, ubB = CUDART_INF_F;
        #pragma unroll 4
        for (int i = 0; i < 32; i++) {
            int f = i * 32 + lane;
            const float4* tq = reinterpret_cast<const float4*>(&g_tri[f * 12]);
            float4 q0 = __ldg(&tq[0]);
            float dxa = px0 - q0.x, dya = py0 - q0.y, dza = pz0 - q0.z;
            float dxb = px1 - q0.x, dyb = py1 - q0.y, dzb = pz1 - q0.z;
            ubA = fminf(ubA, fmaf(dxa, dxa, fmaf(dya, dya, dza * dza)));
            ubB = fminf(ubB, fmaf(dxb, dxb, fmaf(dyb, dyb, dzb * dzb)));
        }
        #pragma unroll
        for (int o = 16; o > 0; o >>= 1) {
            ubA = fminf(ubA, __shfl_xor_sync(0xFFFFFFFFu, ubA, o));
            ubB = fminf(ubB, __shfl_xor_sync(0xFFFFFFFFu, ubB, o));
        }
        float sq0 = fmaf(sqrtf(ubA), 1.001f, 1e-6f);
        float sq1 = fmaf(sqrtf(ubB), 1.001f, 1e-6f);

        unsigned long long bk0 = 0xFFFFFFFFFFFFFFFFull, bk1 = 0xFFFFFFFFFFFFFFFFull;
        float bs0 = 0.0f, bs1 = 0.0f;

        int qnA = 0, qhA = 0, qnB = 0, qhB = 0;

        // Prime the prefetch pipeline
        float4 pl0 = __ldg(&g_plane[lane]);
        float4 pl1 = __ldg(&g_plane[lane + 32]);
        float4 pl2 = __ldg(&g_plane[lane + 64]);
        float4 pl3 = __ldg(&g_plane[lane + 96]);

        for (int chunk = 0; chunk < NF; chunk += 128) {
            // 4 planes x 2 points = 8 independent FMA chains
            float s00 = fmaf(px0, pl0.x, fmaf(py0, pl0.y, fmaf(pz0, pl0.z, pl0.w)));
            float s01 = fmaf(px0, pl1.x, fmaf(py0, pl1.y, fmaf(pz0, pl1.z, pl1.w)));
            float s02 = fmaf(px0, pl2.x, fmaf(py0, pl2.y, fmaf(pz0, pl2.z, pl2.w)));
            float s03 = fmaf(px0, pl3.x, fmaf(py0, pl3.y, fmaf(pz0, pl3.z, pl3.w)));
            float s10 = fmaf(px1, pl0.x, fmaf(py1, pl0.y, fmaf(pz1, pl0.z, pl0.w)));
            float s11 = fmaf(px1, pl1.x, fmaf(py1, pl1.y, fmaf(pz1, pl1.z, pl1.w)));
            float s12 = fmaf(px1, pl2.x, fmaf(py1, pl2.y, fmaf(pz1, pl2.z, pl2.w)));
            float s13 = fmaf(px1, pl3.x, fmaf(py1, pl3.y, fmaf(pz1, pl3.z, pl3.w)));
            bool a0 = (fabsf(s00) <= sq0);
            bool a1 = (fabsf(s01) <= sq0);
            bool a2 = (fabsf(s02) <= sq0);
            bool a3 = (fabsf(s03) <= sq0);
            bool b0 = (fabsf(s10) <= sq1);
            bool b1 = (fabsf(s11) <= sq1);
            bool b2 = (fabsf(s12) <= sq1);
            bool b3 = (fabsf(s13) <= sq1);

            // Prefetch next chunk's planes
            int nxt = chunk + 128;
            if (nxt < NF) {
                pl0 = __ldg(&g_plane[nxt + lane]);
                pl1 = __ldg(&g_plane[nxt + lane + 32]);
                pl2 = __ldg(&g_plane[nxt + lane + 64]);
                pl3 = __ldg(&g_plane[nxt + lane + 96]);
            }

            // Per-point any ballots: skip compaction for a point with no survivors
            unsigned anyA = __ballot_sync(0xFFFFFFFFu, a0 | a1 | a2 | a3);
            unsigned anyB = __ballot_sync(0xFFFFFFFFu, b0 | b1 | b2 | b3);
            if (!(anyA | anyB)) continue;

            if (anyA) {
                unsigned m0 = __ballot_sync(0xFFFFFFFFu, a0);
                unsigned m1 = __ballot_sync(0xFFFFFFFFu, a1);
                unsigned m2 = __ballot_sync(0xFFFFFFFFu, a2);
                unsigned m3 = __ballot_sync(0xFFFFFFFFu, a3);
                int n0 = __popc(m0);
                int n1 = __popc(m1);
                int n2 = __popc(m2);
                if (a0) queueA[w][(qhA + qnA + __popc(m0 & lanemask)) & (QCAP - 1)] = chunk + lane;
                if (a1) queueA[w][(qhA + qnA + n0 + __popc(m1 & lanemask)) & (QCAP - 1)] = chunk + lane + 32;
                if (a2) queueA[w][(qhA + qnA + n0 + n1 + __popc(m2 & lanemask)) & (QCAP - 1)] = chunk + lane + 64;
                if (a3) queueA[w][(qhA + qnA + n0 + n1 + n2 + __popc(m3 & lanemask)) & (QCAP - 1)] = chunk + lane + 96;
                qnA += n0 + n1 + n2 + __popc(m3);
            }
            if (anyB) {
                unsigned m0 = __ballot_sync(0xFFFFFFFFu, b0);
                unsigned m1 = __ballot_sync(0xFFFFFFFFu, b1);
                unsigned m2 = __ballot_sync(0xFFFFFFFFu, b2);
                unsigned m3 = __ballot_sync(0xFFFFFFFFu, b3);
                int n0 = __popc(m0);
                int n1 = __popc(m1);
                int n2 = __popc(m2);
                if (b0) queueB[w][(qhB + qnB + __popc(m0 & lanemask)) & (QCAP - 1)] = chunk + lane;
                if (b1) queueB[w][(qhB + qnB + n0 + __popc(m1 & lanemask)) & (QCAP - 1)] = chunk + lane + 32;
                if (b2) queueB[w][(qhB + qnB + n0 + n1 + __popc(m2 & lanemask)) & (QCAP - 1)] = chunk + lane + 64;
                if (b3) queueB[w][(qhB + qnB + n0 + n1 + n2 + __popc(m3 & lanemask)) & (QCAP - 1)] = chunk + lane + 96;
                qnB += n0 + n1 + n2 + __popc(m3);
            }
            __syncwarp();

            while (qnA >= 32) {
                int fe = queueA[w][(qhA + lane) & (QCAP - 1)];
                qhA += 32;
                qnA -= 32;
                bool imp = eval_tri(fe, px0, py0, pz0, bk0, bs0);
                if (__ballot_sync(0xFFFFFFFFu, imp)) tighten(bk0, sq0);
            }
            while (qnB >= 32) {
                int fe = queueB[w][(qhB + lane) & (QCAP - 1)];
                qhB += 32;
                qnB -= 32;
                bool imp = eval_tri(fe, px1, py1, pz1, bk1, bs1);
                if (__ballot_sync(0xFFFFFFFFu, imp)) tighten(bk1, sq1);
            }
        }

        // Drain leftovers
        __syncwarp();
        if (lane < qnA) {
            int fe = queueA[w][(qhA + lane) & (QCAP - 1)];
            eval_tri(fe, px0, py0, pz0, bk0, bs0);
        }
        if (lane < qnB) {
            int fe = queueB[w][(qhB + lane) & (QCAP - 1)];
            eval_tri(fe, px1, py1, pz1, bk1, bs1);
        }
        __syncwarp();

        // Warp-reduce both (key, sd) lexicographic mins — argmin tie-break
        #pragma unroll
        for (int o = 16; o > 0; o >>= 1) {
            unsigned long long ok = __shfl_xor_sync(0xFFFFFFFFu, bk0, o);
            float osd = __shfl_xor_sync(0xFFFFFFFFu, bs0, o);
            if (ok < bk0) { bk0 = ok; bs0 = osd; }
            unsigned long long ok1 = __shfl_xor_sync(0xFFFFFFFFu, bk1, o);
            float osd1 = __shfl_xor_sync(0xFFFFFFFFu, bs1, o);
            if (ok1 < bk1) { bk1 = ok1; bs1 = osd1; }
        }

        if (lane == 0) {
            float d20 = __uint_as_float((unsigned)(bk0 >> 32));
            float dist0 = sqrtf(fmaxf(d20, 1e-12f));
            out[pid0] = (bs0 > 0.0f) ? -dist0 : dist0;
            float d21 = __uint_as_float((unsigned)(bk1 >> 32));
            float dist1 = sqrtf(fmaxf(d21, 1e-12f));
            out[pid1] = (bs1 > 0.0f) ? -dist1 : dist1;
        }
    }
}

extern "C" void kernel_launch(void* const* d_in, const int* in_sizes, int n_in,
                              void* d_out, int out_size) {
    const float* points   = (const float*)d_in[0];
    const float* vertices = (const float*)d_in[1];
    const int*   faces    = (const int*)d_in[2];
    float* out = (float*)d_out;

    precompute_tris<<<(NF + 255) / 256, 256>>>(vertices, faces);
    sdf_main<<<NBLK, TPB>>>(points, out);
}